// round 17
// baseline (speedup 1.0000x reference)
#include <cuda_runtime.h>
#include <cuda_fp16.h>
#include <cooperative_groups.h>
#include <math.h>

namespace cg = cooperative_groups;

// Problem constants (fixed by the reference)
#define NN 100000      // nodes
#define NE 1600000     // edges
#define FI 192         // input feats (64 latent + 128 X)
#define FH 128         // hidden feats
#define BN_EPS 1e-5f

#define PRE_BLOCKS 196
#define PRE_THREADS 512           // 196*512 = 100352 >= NN+1

// ---------------- device scratch (no allocs allowed) ----------------
__device__ __align__(128) __half g_h1h  [(size_t)NN * FH];  // 25.6 MB (fp16 gather payload)
__device__ __align__(128) __half g_agg1h[(size_t)NN * FH];  // 25.6 MB (fp16 post-agg payload)
__device__ __align__(16)  float  g_h2  [(size_t)NN * 2];
__device__ __align__(16)  float  g_agg2[(size_t)NN * 2];
__device__ float g_dinv[NN];
__device__ int   g_deg [NN];     // zeroed by k_agg2_out tail each call (static init covers call 1)
__device__ int   g_rowptr[NN + 1];
__device__ int   g_rowcur[NN];   // running CSR cursor for scatter atomics
__device__ int   g_esrc[NE];     // CSR by dst: src node only (norm factored:
                                 // agg[d]=dinv[d]*(Σ dinv[s]h[s]+dinv[d]h[d]))
__device__ int   g_bsum[256];    // scan block sums (PRE_BLOCKS used)
__device__ float g_sum1[FH], g_sq1[FH];
__device__ float g_sum2[2], g_sq2[2];

// ---------------- mma helpers ----------------
__device__ __forceinline__ void ldsm_x4(unsigned* r, const void* p) {
    unsigned a = (unsigned)__cvta_generic_to_shared(p);
    asm volatile("ldmatrix.sync.aligned.m8n8.x4.shared.b16 {%0,%1,%2,%3}, [%4];"
                 : "=r"(r[0]), "=r"(r[1]), "=r"(r[2]), "=r"(r[3]) : "r"(a));
}
__device__ __forceinline__ void ldsm_x4_t(unsigned* r, const void* p) {
    unsigned a = (unsigned)__cvta_generic_to_shared(p);
    asm volatile("ldmatrix.sync.aligned.m8n8.x4.trans.shared.b16 {%0,%1,%2,%3}, [%4];"
                 : "=r"(r[0]), "=r"(r[1]), "=r"(r[2]), "=r"(r[3]) : "r"(a));
}
__device__ __forceinline__ void mma16816(float* c, const unsigned* a, const unsigned* b) {
    asm volatile("mma.sync.aligned.m16n8k16.row.col.f32.f16.f16.f32 "
                 "{%0,%1,%2,%3}, {%4,%5,%6,%7}, {%8,%9}, {%0,%1,%2,%3};"
                 : "+f"(c[0]), "+f"(c[1]), "+f"(c[2]), "+f"(c[3])
                 : "r"(a[0]), "r"(a[1]), "r"(a[2]), "r"(a[3]), "r"(b[0]), "r"(b[1]));
}

// ---------------- fused preprocessing (cooperative): degree -> scan -> scatter ----------------
__global__ void k_preproc(const int* __restrict__ ew) {
    cg::grid_group grid = cg::this_grid();
    __shared__ int s[PRE_THREADS];
    __shared__ int sb[256];
    __shared__ int sflag;

    int tid  = threadIdx.x;
    int gtid = blockIdx.x * PRE_THREADS + tid;
    int nthr = PRE_BLOCKS * PRE_THREADS;

    // edge-dtype detect: int64 little-endian => high words of first 32 entries zero
    if (tid == 0) {
        int z = 0;
#pragma unroll
        for (int e = 0; e < 32; e++) z |= ew[2 * e + 1];
        sflag = (z == 0) ? 1 : 0;
    }
    __syncthreads();
    int is64 = sflag;

    // ---- phase A: zero stats accumulators + degree histogram ----
    if (gtid < FH) { g_sum1[gtid] = 0.f; g_sq1[gtid] = 0.f; }
    if (gtid < 2)  { g_sum2[gtid] = 0.f; g_sq2[gtid] = 0.f; }
    for (int e = gtid; e < NE; e += nthr) {
        int d = is64 ? ew[2 * ((size_t)NE + e)] : ew[(size_t)NE + e];
        atomicAdd(&g_deg[d], 1);
    }
    grid.sync();

    // ---- phase B: per-block inclusive scan of 512 degrees (+ dinv) ----
    {
        int i = gtid;
        int v = 0;
        if (i < NN) {
            v = g_deg[i];
            g_dinv[i] = rsqrtf((float)(v + 1));
        }
        s[tid] = v;
        __syncthreads();
#pragma unroll
        for (int o = 1; o < PRE_THREADS; o <<= 1) {
            int t = (tid >= o) ? s[tid - o] : 0;
            __syncthreads();
            s[tid] += t;
            __syncthreads();
        }
        if (i < NN) g_rowptr[i] = s[tid] - v;              // block-local exclusive
        if (tid == PRE_THREADS - 1) g_bsum[blockIdx.x] = s[tid];
    }
    grid.sync();

    // ---- phase C: redundant scan of block sums; finalize rowptr + seed rowcur ----
    {
        if (tid < 256) sb[tid] = (tid < PRE_BLOCKS) ? g_bsum[tid] : 0;
        __syncthreads();
#pragma unroll
        for (int o = 1; o < 256; o <<= 1) {
            int v = 0;
            if (tid < 256 && tid >= o) v = sb[tid - o];
            __syncthreads();
            if (tid < 256) sb[tid] += v;                   // inclusive
            __syncthreads();
        }
        int i = gtid;
        if (i < NN) {
            int b   = blockIdx.x;
            int off = b ? sb[b - 1] : 0;
            int rp  = g_rowptr[i] + off;
            g_rowptr[i] = rp;
            g_rowcur[i] = rp;
        }
        if (i == NN) g_rowptr[NN] = NE;
    }
    grid.sync();

    // ---- phase D: scatter edges into CSR (single atomic per edge) ----
    for (int e = gtid; e < NE; e += nthr) {
        int sN, d;
        if (is64) { sN = ew[2 * (size_t)e];  d = ew[2 * ((size_t)NE + e)]; }
        else      { sN = ew[(size_t)e];      d = ew[(size_t)NE + e]; }
        int pos = atomicAdd(&g_rowcur[d], 1);
        g_esrc[pos] = sN;
    }
}

// ---------------- GEMM1 (tensor cores, register-prefetch pipelined) ----------------
#define SA_LD 40     // 32 + 8 halves padding
#define SB_LD 136    // 128 + 8 halves padding
__global__ __launch_bounds__(256, 2)
void k_gemm1(const float* __restrict__ X, const float* __restrict__ uY,
             const float* __restrict__ W1) {
    __shared__ __half sA[128][SA_LD];
    __shared__ __half sB[32][SB_LD];
    int tid   = threadIdx.x;
    int lane  = tid & 31;
    int wid   = tid >> 5;
    int warp_m = wid >> 1;          // 0..3
    int warp_n = wid & 1;           // 0..1
    int m0 = blockIdx.x * 128;

    int aNode[4], aK4[4], bK[4], bC4[4];
#pragma unroll
    for (int r = 0; r < 4; r++) {
        int idx = tid + r * 256;
        aNode[r] = idx >> 3;  aK4[r] = idx & 7;
        bK[r]    = idx >> 5;  bC4[r] = idx & 31;
    }
    int gnc[4];
#pragma unroll
    for (int r = 0; r < 4; r++) {
        int gn = m0 + aNode[r];
        gnc[r] = gn < NN ? gn : NN - 1;
    }

    float4 pa[4], pb[4];
#pragma unroll
    for (int r = 0; r < 4; r++) {
        int k = aK4[r] * 4;
        pa[r] = (k < 64) ? *(const float4*)(uY + (size_t)gnc[r] * 64 + k)
                         : *(const float4*)(X  + (size_t)gnc[r] * 128 + (k - 64));
        pb[r] = *(const float4*)(W1 + (size_t)bK[r] * FH + bC4[r] * 4);
    }

    float acc[2][8][4];
#pragma unroll
    for (int mi = 0; mi < 2; mi++)
#pragma unroll
        for (int ni = 0; ni < 8; ni++)
#pragma unroll
            for (int r = 0; r < 4; r++) acc[mi][ni][r] = 0.f;

    for (int kc = 0; kc < FI; kc += 32) {
        __syncthreads();
#pragma unroll
        for (int r = 0; r < 4; r++) {
            *(__half2*)&sA[aNode[r]][aK4[r] * 4]     = __floats2half2_rn(pa[r].x, pa[r].y);
            *(__half2*)&sA[aNode[r]][aK4[r] * 4 + 2] = __floats2half2_rn(pa[r].z, pa[r].w);
            *(__half2*)&sB[bK[r]][bC4[r] * 4]        = __floats2half2_rn(pb[r].x, pb[r].y);
            *(__half2*)&sB[bK[r]][bC4[r] * 4 + 2]    = __floats2half2_rn(pb[r].z, pb[r].w);
        }
        __syncthreads();

        int kn = kc + 32;
        if (kn < FI) {
#pragma unroll
            for (int r = 0; r < 4; r++) {
                int k = kn + aK4[r] * 4;
                pa[r] = (k < 64) ? *(const float4*)(uY + (size_t)gnc[r] * 64 + k)
                                 : *(const float4*)(X  + (size_t)gnc[r] * 128 + (k - 64));
                pb[r] = *(const float4*)(W1 + (size_t)(kn + bK[r]) * FH + bC4[r] * 4);
            }
        }

#pragma unroll
        for (int ck = 0; ck < 32; ck += 16) {
            unsigned a[2][4];
#pragma unroll
            for (int mi = 0; mi < 2; mi++) {
                int row = warp_m * 32 + mi * 16 + (lane & 15);
                int col = ck + (lane >> 4) * 8;
                ldsm_x4(a[mi], &sA[row][col]);
            }
            unsigned b[8][2];
#pragma unroll
            for (int bi = 0; bi < 4; bi++) {
                unsigned t4[4];
                int krow = ck + (lane & 15);
                int ncol = warp_n * 64 + bi * 16 + (lane >> 4) * 8;
                ldsm_x4_t(t4, &sB[krow][ncol]);
                b[2 * bi][0]     = t4[0]; b[2 * bi][1]     = t4[1];
                b[2 * bi + 1][0] = t4[2]; b[2 * bi + 1][1] = t4[3];
            }
#pragma unroll
            for (int mi = 0; mi < 2; mi++)
#pragma unroll
                for (int ni = 0; ni < 8; ni++)
                    mma16816(acc[mi][ni], a[mi], b[ni]);
        }
    }

#pragma unroll
    for (int mi = 0; mi < 2; mi++) {
        int row = m0 + warp_m * 32 + mi * 16 + (lane >> 2);
#pragma unroll
        for (int ni = 0; ni < 8; ni++) {
            int col = warp_n * 64 + ni * 8 + (lane & 3) * 2;
            if (row < NN)
                *(__half2*)(g_h1h + (size_t)row * FH + col) =
                    __floats2half2_rn(acc[mi][ni][0], acc[mi][ni][1]);
            if (row + 8 < NN)
                *(__half2*)(g_h1h + (size_t)(row + 8) * FH + col) =
                    __floats2half2_rn(acc[mi][ni][2], acc[mi][ni][3]);
        }
    }
}

// ---------------- layer-1 aggregation: warp per dst row, 2 edges in flight ----------------
__global__ __launch_bounds__(256)
void k_agg1() {
    int gtid  = blockIdx.x * blockDim.x + threadIdx.x;
    int lane  = threadIdx.x & 31;
    int half  = lane >> 4;
    int fl    = lane & 15;
    int wid   = gtid >> 5;
    int nwarp = (gridDim.x * blockDim.x) >> 5;

    for (int row = wid; row < NN; row += nwarp) {
        int start = g_rowptr[row];
        int end   = g_rowptr[row + 1];
        float dinv_row = g_dinv[row];

        float a0 = 0.f, a1 = 0.f, a2 = 0.f, a3 = 0.f;
        float a4 = 0.f, a5 = 0.f, a6 = 0.f, a7 = 0.f;
        if (half == 0) {
            float c = dinv_row;
            uint4 raw = *((const uint4*)(g_h1h + (size_t)row * FH) + fl);
            float2 f;
            f = __half22float2(*(const __half2*)&raw.x); a0 = f.x * c; a1 = f.y * c;
            f = __half22float2(*(const __half2*)&raw.y); a2 = f.x * c; a3 = f.y * c;
            f = __half22float2(*(const __half2*)&raw.z); a4 = f.x * c; a5 = f.y * c;
            f = __half22float2(*(const __half2*)&raw.w); a6 = f.x * c; a7 = f.y * c;
        }

        for (int i = start + half; i < end + half; i += 2) {
            int   s = (i < end) ? g_esrc[i] : row;
            float c = (i < end) ? g_dinv[s] : 0.f;
            uint4 r = *((const uint4*)(g_h1h + (size_t)s * FH) + fl);
            float2 f;
            f = __half22float2(*(const __half2*)&r.x); a0 = fmaf(f.x, c, a0); a1 = fmaf(f.y, c, a1);
            f = __half22float2(*(const __half2*)&r.y); a2 = fmaf(f.x, c, a2); a3 = fmaf(f.y, c, a3);
            f = __half22float2(*(const __half2*)&r.z); a4 = fmaf(f.x, c, a4); a5 = fmaf(f.y, c, a5);
            f = __half22float2(*(const __half2*)&r.w); a6 = fmaf(f.x, c, a6); a7 = fmaf(f.y, c, a7);
        }

        a0 += __shfl_xor_sync(0xffffffffu, a0, 16);
        a1 += __shfl_xor_sync(0xffffffffu, a1, 16);
        a2 += __shfl_xor_sync(0xffffffffu, a2, 16);
        a3 += __shfl_xor_sync(0xffffffffu, a3, 16);
        a4 += __shfl_xor_sync(0xffffffffu, a4, 16);
        a5 += __shfl_xor_sync(0xffffffffu, a5, 16);
        a6 += __shfl_xor_sync(0xffffffffu, a6, 16);
        a7 += __shfl_xor_sync(0xffffffffu, a7, 16);

        if (half == 0) {
            uint4 o;
            *(__half2*)&o.x = __floats2half2_rn(a0 * dinv_row, a1 * dinv_row);
            *(__half2*)&o.y = __floats2half2_rn(a2 * dinv_row, a3 * dinv_row);
            *(__half2*)&o.z = __floats2half2_rn(a4 * dinv_row, a5 * dinv_row);
            *(__half2*)&o.w = __floats2half2_rn(a6 * dinv_row, a7 * dinv_row);
            *((uint4*)(g_agg1h + (size_t)row * FH) + fl) = o;
        }
    }
}

// ---------------- fused BN1 stats + apply + GEMM2 (cooperative) ----------------
#define BL_BLOCKS 512
__global__ __launch_bounds__(256)
void k_bn1_layer2(const float* __restrict__ W2,
                  const float* __restrict__ gamma1, const float* __restrict__ beta1) {
    cg::grid_group grid = cg::this_grid();
    int tid  = threadIdx.x;
    int lane = tid & 31;

    // ---- phase 1: column stats (proven atomic density: ~1K lane-ops/address) ----
    {
        int j    = tid & 127;          // feature
        int half = tid >> 7;           // 0/1 row-interleave
        float s = 0.f, q = 0.f;
        for (int n = blockIdx.x * 2 + half; n < NN; n += gridDim.x * 2) {
            float v = __half2float(g_agg1h[(size_t)n * FH + j]);
            s += v;
            q = fmaf(v, v, q);
        }
        atomicAdd(&g_sum1[j], s);
        atomicAdd(&g_sq1[j], q);
    }
    grid.sync();

    // ---- phase 2: BN1 apply + ReLU + GEMM2 -> h2 (warp per node) ----
    int f = lane * 4;
    float4 sm = *(const float4*)&g_sum1[f];
    float4 sq = *(const float4*)&g_sq1[f];
    float4 gm = *(const float4*)&gamma1[f];
    float4 bt = *(const float4*)&beta1[f];
    float4 sc, sh;
    {
        float m, v;
        m = sm.x * (1.f / NN); v = sq.x * (1.f / NN) - m * m; sc.x = gm.x * rsqrtf(v + BN_EPS); sh.x = bt.x - m * sc.x;
        m = sm.y * (1.f / NN); v = sq.y * (1.f / NN) - m * m; sc.y = gm.y * rsqrtf(v + BN_EPS); sh.y = bt.y - m * sc.y;
        m = sm.z * (1.f / NN); v = sq.z * (1.f / NN) - m * m; sc.z = gm.z * rsqrtf(v + BN_EPS); sh.z = bt.z - m * sc.z;
        m = sm.w * (1.f / NN); v = sq.w * (1.f / NN) - m * m; sc.w = gm.w * rsqrtf(v + BN_EPS); sh.w = bt.w - m * sc.w;
    }
    const float4* w4 = (const float4*)W2;
    float4 wA = w4[lane * 2];
    float4 wB = w4[lane * 2 + 1];

    int gtid  = blockIdx.x * blockDim.x + tid;
    int wid   = gtid >> 5;
    int nwarp = (gridDim.x * blockDim.x) >> 5;
    for (int node = wid; node < NN; node += nwarp) {
        uint2 raw = *((const uint2*)(g_agg1h + (size_t)node * FH) + lane);
        float2 f0 = __half22float2(*(const __half2*)&raw.x);
        float2 f1 = __half22float2(*(const __half2*)&raw.y);
        float y0 = fmaxf(fmaf(f0.x, sc.x, sh.x), 0.f);
        float y1 = fmaxf(fmaf(f0.y, sc.y, sh.y), 0.f);
        float y2 = fmaxf(fmaf(f1.x, sc.z, sh.z), 0.f);
        float y3 = fmaxf(fmaf(f1.y, sc.w, sh.w), 0.f);
        float p0 = y0 * wA.x + y1 * wA.z + y2 * wB.x + y3 * wB.z;
        float p1 = y0 * wA.y + y1 * wA.w + y2 * wB.y + y3 * wB.w;
#pragma unroll
        for (int o = 16; o; o >>= 1) {
            p0 += __shfl_xor_sync(0xffffffffu, p0, o);
            p1 += __shfl_xor_sync(0xffffffffu, p1, o);
        }
        if (lane == 0) {
            g_h2[(size_t)node * 2 + 0] = p0;
            g_h2[(size_t)node * 2 + 1] = p1;
        }
    }
}

// ---------------- fused agg2 + BN2 + softmax (cooperative) ----------------
#define AO_BLOCKS 512
__global__ __launch_bounds__(256)
void k_agg2_out(const float* __restrict__ gamma2, const float* __restrict__ beta2,
                float* __restrict__ out) {
    cg::grid_group grid = cg::this_grid();
    __shared__ float red[8][4];
    int lane   = threadIdx.x & 31;
    int warp   = threadIdx.x >> 5;
    int gtid   = blockIdx.x * blockDim.x + threadIdx.x;
    int stride = gridDim.x * blockDim.x;

    // ---- phase 1: layer-2 aggregation + stats ----
    float s0 = 0.f, q0 = 0.f, s1 = 0.f, q1 = 0.f;
    for (int row = gtid; row < NN; row += stride) {
        int start = g_rowptr[row];
        int end   = g_rowptr[row + 1];
        float dinv_row = g_dinv[row];
        float2 h  = *(const float2*)(g_h2 + (size_t)row * 2);
        float a0 = h.x * dinv_row, a1 = h.y * dinv_row;
        int i = start;
        for (; i + 4 <= end; i += 4) {
            int e0 = g_esrc[i],     e1 = g_esrc[i + 1];
            int e2 = g_esrc[i + 2], e3 = g_esrc[i + 3];
            float2 h0 = *(const float2*)(g_h2 + (size_t)e0 * 2);
            float2 h1 = *(const float2*)(g_h2 + (size_t)e1 * 2);
            float2 h2 = *(const float2*)(g_h2 + (size_t)e2 * 2);
            float2 h3 = *(const float2*)(g_h2 + (size_t)e3 * 2);
            float c0 = g_dinv[e0], c1 = g_dinv[e1];
            float c2 = g_dinv[e2], c3 = g_dinv[e3];
            a0 = fmaf(h0.x, c0, fmaf(h1.x, c1, fmaf(h2.x, c2, fmaf(h3.x, c3, a0))));
            a1 = fmaf(h0.y, c0, fmaf(h1.y, c1, fmaf(h2.y, c2, fmaf(h3.y, c3, a1))));
        }
        for (; i < end; i++) {
            int e = g_esrc[i];
            float c = g_dinv[e];
            float2 hs = *(const float2*)(g_h2 + (size_t)e * 2);
            a0 = fmaf(hs.x, c, a0);
            a1 = fmaf(hs.y, c, a1);
        }
        a0 *= dinv_row;
        a1 *= dinv_row;
        g_agg2[(size_t)row * 2 + 0] = a0;
        g_agg2[(size_t)row * 2 + 1] = a1;
        s0 += a0; q0 = fmaf(a0, a0, q0);
        s1 += a1; q1 = fmaf(a1, a1, q1);
    }
#pragma unroll
    for (int o = 16; o; o >>= 1) {
        s0 += __shfl_xor_sync(0xffffffffu, s0, o);
        q0 += __shfl_xor_sync(0xffffffffu, q0, o);
        s1 += __shfl_xor_sync(0xffffffffu, s1, o);
        q1 += __shfl_xor_sync(0xffffffffu, q1, o);
    }
    if (lane == 0) { red[warp][0] = s0; red[warp][1] = q0; red[warp][2] = s1; red[warp][3] = q1; }
    __syncthreads();
    if (warp == 0 && lane < 4) {
        float acc = 0.f;
#pragma unroll
        for (int w = 0; w < 8; w++) acc += red[w][lane];
        float* dst[4] = { &g_sum2[0], &g_sq2[0], &g_sum2[1], &g_sq2[1] };
        atomicAdd(dst[lane], acc);
    }
    grid.sync();

    // ---- phase 2: BN2 + softmax + g_deg self-clean ----
    float m0 = g_sum2[0] * (1.f / NN);
    float v0 = g_sq2[0] * (1.f / NN) - m0 * m0;
    float m1 = g_sum2[1] * (1.f / NN);
    float v1 = g_sq2[1] * (1.f / NN) - m1 * m1;
    float sc0 = gamma2[0] * rsqrtf(v0 + BN_EPS);
    float sc1 = gamma2[1] * rsqrtf(v1 + BN_EPS);
    float sh0 = beta2[0] - m0 * sc0;
    float sh1 = beta2[1] - m1 * sc1;

    for (int i = gtid; i < NN; i += stride) {
        float2 a = *(const float2*)(g_agg2 + (size_t)i * 2);
        float y0 = fmaf(a.x, sc0, sh0);
        float y1 = fmaf(a.y, sc1, sh1);
        float mm = fmaxf(y0, y1);
        float e0 = expf(y0 - mm);
        float e1 = expf(y1 - mm);
        float inv = 1.f / (e0 + e1);
        ((float2*)out)[i] = make_float2(e0 * inv, e1 * inv);
        g_deg[i] = 0;   // self-clean for next replay
    }
}

// ---------------- launch ----------------
extern "C" void kernel_launch(void* const* d_in, const int* in_sizes, int n_in,
                              void* d_out, int out_size) {
    const int*   ew     = (const int*)  d_in[0];   // edge_index (int32 or int64, detected)
    const float* X      = (const float*)d_in[1];
    const float* uY     = (const float*)d_in[2];
    const float* W1     = (const float*)d_in[3];
    // d_in[4] = b1 (cancels under BatchNorm)
    const float* W2     = (const float*)d_in[5];
    // d_in[6] = b2 (cancels under BatchNorm)
    const float* gamma1 = (const float*)d_in[7];
    const float* beta1  = (const float*)d_in[8];
    const float* gamma2 = (const float*)d_in[9];
    const float* beta2  = (const float*)d_in[10];
    float* out = (float*)d_out;

    // Fork GEMM1 (depends only on X/uY/W1) onto a side stream. Handles are
    // deliberately not destroyed (destroying a capture-participating stream
    // invalidates the capture; replays execute no host code).
    cudaStream_t s2;
    cudaStreamCreateWithFlags(&s2, cudaStreamNonBlocking);
    cudaEvent_t eFork, eJoin;
    cudaEventCreateWithFlags(&eFork, cudaEventDisableTiming);
    cudaEventCreateWithFlags(&eJoin, cudaEventDisableTiming);

    cudaEventRecord(eFork, 0);

    // fused CSR preprocessing (cooperative) on the default stream
    {
        void* args[] = { (void*)&ew };
        cudaLaunchCooperativeKernel((void*)k_preproc,
                                    dim3(PRE_BLOCKS), dim3(PRE_THREADS), args, 0, (cudaStream_t)0);
    }

    cudaStreamWaitEvent(s2, eFork, 0);
    k_gemm1<<<(NN + 127) / 128, 256, 0, s2>>>(X, uY, W1);
    cudaEventRecord(eJoin, s2);

    cudaStreamWaitEvent(0, eJoin, 0);     // join: agg1 needs both h1h and CSR

    k_agg1<<<2048, 256>>>();

    {
        void* args[] = { (void*)&W2, (void*)&gamma1, (void*)&beta1 };
        cudaLaunchCooperativeKernel((void*)k_bn1_layer2,
                                    dim3(BL_BLOCKS), dim3(256), args, 0, (cudaStream_t)0);
    }
    {
        void* args[] = { (void*)&gamma2, (void*)&beta2, (void*)&out };
        cudaLaunchCooperativeKernel((void*)k_agg2_out,
                                    dim3(AO_BLOCKS), dim3(256), args, 0, (cudaStream_t)0);
    }
}